// round 3
// baseline (speedup 1.0000x reference)
#include <cuda_runtime.h>

// DistMult edge scoring:
//   out[e] = sigmoid( sum_d h[src[e]][d] * W[rel[e]][d] * h[dst[e]][d] )
// h: [100000, 128] f32, W: [6, 128] f32, src/dst/rel: [E] int32 (JAX default
// x64-disabled: "int64" arrays are actually int32), out: [E] f32
//
// One warp per edge, grid-stride. 128 floats / 32 lanes = one float4/lane.
// Row bases are 512B-aligned -> aligned, fully-coalesced 512B row reads.
// W (3 KB) staged in shared once per block. h (51 MB) is L2-resident, so the
// kernel is bound by L2 gather throughput: 1.5M * 1KB = 1.5 GB of L2 reads.

#define WARPS_PER_BLOCK 8
#define THREADS_PER_BLOCK (WARPS_PER_BLOCK * 32)
#define GRID_BLOCKS (148 * 8)

__global__ __launch_bounds__(THREADS_PER_BLOCK)
void distmult_kernel(const float* __restrict__ h,
                     const float* __restrict__ W,
                     const int* __restrict__ src,
                     const int* __restrict__ dst,
                     const int* __restrict__ rel,
                     float* __restrict__ out,
                     int E)
{
    // Stage W in shared: 6 rels * 32 float4 = 192 float4 = 3 KB
    __shared__ float4 sW[6 * 32];
    int tid = threadIdx.x;
    if (tid < 6 * 32) {
        sW[tid] = reinterpret_cast<const float4*>(W)[tid];
    }
    __syncthreads();

    const int lane      = tid & 31;
    const int warp      = tid >> 5;
    const int warp_glb  = blockIdx.x * WARPS_PER_BLOCK + warp;
    const int warp_step = gridDim.x * WARPS_PER_BLOCK;

    for (int edge = warp_glb; edge < E; edge += warp_step) {
        int s = __ldg(src + edge);
        int d = __ldg(dst + edge);
        int r = __ldg(rel + edge);

        float4 u = __ldg(reinterpret_cast<const float4*>(h) + s * 32 + lane);
        float4 v = __ldg(reinterpret_cast<const float4*>(h) + d * 32 + lane);
        float4 w = sW[r * 32 + lane];

        float sum = u.x * w.x * v.x
                  + u.y * w.y * v.y
                  + u.z * w.z * v.z
                  + u.w * w.w * v.w;

        #pragma unroll
        for (int off = 16; off > 0; off >>= 1)
            sum += __shfl_xor_sync(0xffffffffu, sum, off);

        if (lane == 0) {
            out[edge] = 1.0f / (1.0f + __expf(-sum));
        }
    }
}

extern "C" void kernel_launch(void* const* d_in, const int* in_sizes, int n_in,
                              void* d_out, int out_size)
{
    const float* h   = (const float*)d_in[0];
    const float* W   = (const float*)d_in[1];
    const int*   src = (const int*)d_in[2];
    const int*   dst = (const int*)d_in[3];
    const int*   rel = (const int*)d_in[4];
    float* out = (float*)d_out;

    int E = in_sizes[2];  // number of edges

    int blocks_needed = (E + WARPS_PER_BLOCK - 1) / WARPS_PER_BLOCK;
    int blocks = blocks_needed < GRID_BLOCKS ? blocks_needed : GRID_BLOCKS;
    distmult_kernel<<<blocks, THREADS_PER_BLOCK>>>(h, W, src, dst, rel, out, E);
}